// round 2
// baseline (speedup 1.0000x reference)
#include <cuda_runtime.h>

// ---------------------------------------------------------------------------
// Problem constants (fixed by setup_inputs)
// ---------------------------------------------------------------------------
#define NLEV 5
#define BATCH 128
#define NBOX 64

static __constant__ int   c_H[NLEV]  = {334, 167, 84, 42, 21};
static __constant__ int   c_W[NLEV]  = {200, 100, 50, 25, 13};
// float32(W/800), float32(H/1333) — matches JAX float32 weak-scalar promotion
static __constant__ float c_sx[NLEV] = {
    (float)(200.0 / 800.0), (float)(100.0 / 800.0), (float)(50.0 / 800.0),
    (float)(25.0 / 800.0),  (float)(13.0 / 800.0)};
static __constant__ float c_sy[NLEV] = {
    (float)(334.0 / 1333.0), (float)(167.0 / 1333.0), (float)(84.0 / 1333.0),
    (float)(42.0 / 1333.0),  (float)(21.0 / 1333.0)};
// element counts per level (128*H*W) / 4  (all divisible by 4 -> float4 loads)
static __constant__ int c_N4[NLEV] = {
    (128 * 334 * 200) / 4, (128 * 167 * 100) / 4, (128 * 84 * 50) / 4,
    (128 * 42 * 25) / 4,   (128 * 21 * 13) / 4};

// Sum-phase block partition across levels (proportional to data size)
#define SUM_BLOCKS 640
static __constant__ int c_soff[NLEV + 1] = {0, 480, 600, 630, 638, 640};

#define COUNT_BLOCKS (NLEV * BATCH)   // 640
#define TOTAL_BLOCKS (SUM_BLOCKS + COUNT_BLOCKS)
#define THREADS 256

// ---------------------------------------------------------------------------
// Scratch (no allocations allowed -> device globals)
// ---------------------------------------------------------------------------
__device__ double       g_sum[NLEV];
__device__ unsigned int g_cnt[NLEV];

// ---------------------------------------------------------------------------
__global__ void zero_kernel() {
    int t = threadIdx.x;
    if (t < NLEV) { g_sum[t] = 0.0; g_cnt[t] = 0u; }
}

template <typename T>
__device__ __forceinline__ T block_reduce_sum(T val) {
    __shared__ T sh[32];
    int lane = threadIdx.x & 31;
    int wid  = threadIdx.x >> 5;
#pragma unroll
    for (int o = 16; o > 0; o >>= 1) val += __shfl_down_sync(0xffffffffu, val, o);
    if (lane == 0) sh[wid] = val;
    __syncthreads();
    int nw = blockDim.x >> 5;
    val = (threadIdx.x < (unsigned)nw) ? sh[lane] : T(0);
    if (wid == 0) {
#pragma unroll
        for (int o = 16; o > 0; o >>= 1) val += __shfl_down_sync(0xffffffffu, val, o);
    }
    return val;
}

// Fused kernel: blocks [0, SUM_BLOCKS) reduce the h arrays;
//               blocks [SUM_BLOCKS, TOTAL) compute exact box-union pixel counts.
__global__ void __launch_bounds__(THREADS)
work_kernel(const float* __restrict__ h0, const float* __restrict__ h1,
            const float* __restrict__ h2, const float* __restrict__ h3,
            const float* __restrict__ h4, const float* __restrict__ boxes) {
    int bx = blockIdx.x;

    if (bx < SUM_BLOCKS) {
        // ---- h reduction ----
        int lev = 0;
        while (bx >= c_soff[lev + 1]) lev++;
        int inner = bx - c_soff[lev];
        int nblk  = c_soff[lev + 1] - c_soff[lev];
        const float* hp;
        switch (lev) {
            case 0: hp = h0; break;
            case 1: hp = h1; break;
            case 2: hp = h2; break;
            case 3: hp = h3; break;
            default: hp = h4; break;
        }
        const float4* p = reinterpret_cast<const float4*>(hp);
        int n4     = c_N4[lev];
        int stride = nblk * THREADS;
        float s = 0.0f;
        for (int i = inner * THREADS + threadIdx.x; i < n4; i += stride) {
            float4 v = p[i];
            s += (v.x + v.y) + (v.z + v.w);
        }
        s = block_reduce_sum<float>(s);
        if (threadIdx.x == 0) atomicAdd(&g_sum[lev], (double)s);
    } else {
        // ---- exact coverage count: one block per (level, batch) ----
        int t   = bx - SUM_BLOCKS;
        int lev = t >> 7;        // /128
        int b   = t & 127;       // %128
        int H = c_H[lev], W = c_W[lev];
        float sx = c_sx[lev], sy = c_sy[lev];
        (void)W;

        __shared__ int s_x1[NBOX], s_x2[NBOX], s_y1[NBOX], s_y2[NBOX];
        int tid = threadIdx.x;
        if (tid < NBOX) {
            const float* bp = boxes + ((size_t)b * NBOX + tid) * 4;
            float fx1 = fminf(fmaxf(rintf(bp[0] * sx), 0.0f), (float)(W - 1));
            float fy1 = fminf(fmaxf(rintf(bp[1] * sy), 0.0f), (float)(H - 1));
            float fx2 = fminf(fmaxf(rintf(bp[2] * sx), 0.0f), (float)W);
            float fy2 = fminf(fmaxf(rintf(bp[3] * sy), 0.0f), (float)H);
            int ix1 = (int)fx1, iy1 = (int)fy1, ix2 = (int)fx2, iy2 = (int)fy2;
            bool valid = (fx2 > fx1) && (fy2 > fy1);
            if (!valid) { iy1 = 0x7fffffff; iy2 = -1; }
            s_x1[tid] = ix1; s_x2[tid] = ix2; s_y1[tid] = iy1; s_y2[tid] = iy2;
        }
        __syncthreads();

        unsigned int cnt = 0;
        for (int r = tid; r < H; r += THREADS) {
            unsigned int w[7] = {0, 0, 0, 0, 0, 0, 0};
#pragma unroll 4
            for (int m = 0; m < NBOX; m++) {
                if (r >= s_y1[m] && r < s_y2[m]) {
                    int a = s_x1[m], e = s_x2[m];
#pragma unroll
                    for (int wi = 0; wi < 7; wi++) {
                        int lo = a - wi * 32;
                        int hi = e - wi * 32;
                        lo = lo < 0 ? 0 : lo;
                        hi = hi > 32 ? 32 : hi;
                        if (hi > lo) {
                            unsigned int hm =
                                (hi == 32) ? 0xFFFFFFFFu : ((1u << hi) - 1u);
                            w[wi] |= hm & (0xFFFFFFFFu << lo);
                        }
                    }
                }
            }
#pragma unroll
            for (int wi = 0; wi < 7; wi++) cnt += (unsigned)__popc(w[wi]);
        }
        cnt = block_reduce_sum<unsigned int>(cnt);
        if (tid == 0) atomicAdd(&g_cnt[lev], cnt);
    }
}

__global__ void finalize_kernel(float* __restrict__ out) {
    double acc = 0.0;
#pragma unroll
    for (int lev = 0; lev < NLEV; lev++) {
        double tn = (double)BATCH * (double)c_H[lev] * (double)c_W[lev];
        double mh = g_sum[lev] / tn;
        double pi = (double)g_cnt[lev] / tn;
        double d  = mh - pi;
        acc += d * d;
    }
    out[0] = (float)(acc / (double)NLEV);
}

// ---------------------------------------------------------------------------
extern "C" void kernel_launch(void* const* d_in, const int* in_sizes, int n_in,
                              void* d_out, int out_size) {
    (void)in_sizes; (void)n_in; (void)out_size;
    const float* h0    = (const float*)d_in[0];
    const float* h1    = (const float*)d_in[1];
    const float* h2    = (const float*)d_in[2];
    const float* h3    = (const float*)d_in[3];
    const float* h4    = (const float*)d_in[4];
    const float* boxes = (const float*)d_in[5];
    float* out = (float*)d_out;

    zero_kernel<<<1, 32>>>();
    work_kernel<<<TOTAL_BLOCKS, THREADS>>>(h0, h1, h2, h3, h4, boxes);
    finalize_kernel<<<1, 1>>>(out);
}